// round 11
// baseline (speedup 1.0000x reference)
#include <cuda_runtime.h>
#include <cuda_bf16.h>
#include <stdint.h>
#include <math.h>

// Problem constants
#define BB 8
#define SS 512
#define DD 1024
#define FF 4096
#define EE 8
#define HH 16
#define NTOK 4096              // B*S
#define NSLOT 8192             // NTOK * top2
#define MAXPAD 9216            // 8192 + 8*128 padding
#define MAXMT 72               // MAXPAD/128

// ---------------- scratch (device globals; no allocation) ----------------
__device__ float g_hln  [NTOK * DD];
__device__ float g_qkv  [NTOK * 3 * DD];
__device__ float g_attn [NTOK * DD];
__device__ float g_xres [NTOK * DD];
__device__ float g_moein[NTOK * DD];    // tf32-rounded (GEMM A)
__device__ float g_moeraw[NTOK * DD];   // unrounded (gate input)
__device__ float g_h1  [MAXPAD * FF];
__device__ float g_y   [MAXPAD * DD];

// tf32-rounded, transposed (K-major, [N][K]) weights
__device__ float g_wt_qkv[3 * DD * DD];
__device__ float g_wt_o  [DD * DD];
__device__ float g_wt1   [EE * FF * DD];   // per e: [F][D]
__device__ float g_wt2   [EE * DD * FF];   // per e: [D][F]

__device__ int   g_top_e[NSLOT];
__device__ float g_top_w[NSLOT];
__device__ int   g_counts[EE];
__device__ int   g_pad_off[EE + 1];
__device__ int   g_tile_expert[MAXMT];
__device__ int   g_n_mtiles;
__device__ int   g_tok_of_slot[MAXPAD];
__device__ int   g_slot_of[NSLOT];

// ---------------- helpers ----------------
__device__ __forceinline__ uint32_t smem_u32(const void* p) {
    uint32_t a;
    asm("{ .reg .u64 t; cvta.to.shared.u64 t, %1; cvt.u32.u64 %0, t; }" : "=r"(a) : "l"(p));
    return a;
}
__device__ __forceinline__ uint32_t f2tf(float f) {
    uint32_t u;
    asm("cvt.rna.tf32.f32 %0, %1;" : "=r"(u) : "f"(f));
    return u;
}
__device__ __forceinline__ float f2tf_f(float f) { return __uint_as_float(f2tf(f)); }
__device__ __forceinline__ float gelu_tanh(float v) {
    const float c = 0.7978845608028654f;
    float u = c * (v + 0.044715f * v * v * v);
    return 0.5f * v * (1.0f + tanhf(u));
}

// ---------------- weight transpose + tf32 round: src[R][C] -> dst[C][R] ----------------
__global__ __launch_bounds__(256)
void transpose_round(const float* __restrict__ src, float* __restrict__ dst, int R, int C) {
    __shared__ float t[32][33];
    const float* s = src + (size_t)blockIdx.z * R * C;
    float*       d = dst + (size_t)blockIdx.z * R * C;
    int r0 = blockIdx.y * 32, c0 = blockIdx.x * 32;
    int tx = threadIdx.x, ty = threadIdx.y;         // 32 x 8
    #pragma unroll
    for (int i = 0; i < 32; i += 8)
        t[ty + i][tx] = s[(size_t)(r0 + ty + i) * C + c0 + tx];
    __syncthreads();
    #pragma unroll
    for (int i = 0; i < 32; i += 8)
        d[(size_t)(c0 + ty + i) * R + r0 + tx] = f2tf_f(t[tx][ty + i]);
}

// ============ tf32 mma.sync GEMM: 128x128 CTA, 256 thr, warp 64x32 (2x4), 2 CTA/SM ============
// Both A and Wt are tf32-rounded fp32; Wt is K-major [N][K].
// MODE 0: C = A*B            MODE 1: C = A*B + aux
// MODE 2: C = gelu(Agather*B+b1), output tf32-rounded
// MODE 3: C = A*B + b2
#define MM_STAGE_BYTES 32768   // 16KB A + 16KB B
#define MM_SMEM_BYTES  65536   // 2 stages

template<int MODE, int KDIM, int NDIM>
__global__ __launch_bounds__(256, 2)
void gemm_mma(const float* __restrict__ A, const float* __restrict__ Wt,
              const float* __restrict__ aux, float* __restrict__ C) {
    int mt = blockIdx.y;
    if (MODE >= 2 && mt >= g_n_mtiles) return;
    const float* Wb = Wt;
    const float* bias = aux;
    if (MODE >= 2) {
        int e = g_tile_expert[mt];
        Wb   = Wt + (size_t)e * KDIM * NDIM;
        bias = aux + (size_t)e * NDIM;
    }
    extern __shared__ __align__(16) char smem[];
    uint32_t sbase = smem_u32(smem);

    int tid = threadIdx.x;
    int lane = tid & 31, wid = tid >> 5;
    int bm = mt * 128, bn = blockIdx.x * 128;

    // ---- fill mapping: rg = row group (0..31), cc = float4 chunk (0..7) ----
    int rg = tid >> 3, cc = tid & 7;
    const float* arow[4];
    const float* brow[4];
    #pragma unroll
    for (int i = 0; i < 4; i++) {
        int r = rg + i * 32;
        int m = (MODE == 2) ? g_tok_of_slot[bm + r] : (bm + r);
        arow[i] = A  + (size_t)m * KDIM + cc * 4;
        brow[i] = Wb + (size_t)(bn + r) * KDIM + cc * 4;
    }
    uint32_t sw = (uint32_t)(((cc ^ (rg & 7)) << 4) + rg * 128);

    // ---- fragment read bases (ldmatrix), warp grid 2 (M) x 4 (N), warp tile 64x32 ----
    int wr = wid & 1, wc = wid >> 1;
    int rowa_base = wr * 64 + (lane & 7) + ((lane >> 3) & 1) * 8;
    int lhiA = lane >> 4;
    uint32_t aswz = (uint32_t)((rowa_base & 7) << 4);
    // B x4-pair: covers 16 n-rows per ldmatrix.x4
    int rowb2 = wc * 32 + (lane & 7) + ((lane >> 4) & 1) * 8;
    int lbB = (lane >> 3) & 1;
    uint32_t bswz = (uint32_t)((lane & 7) << 4);

    float acc[4][4][4];
    #pragma unroll
    for (int mi = 0; mi < 4; mi++)
        #pragma unroll
        for (int ni = 0; ni < 4; ni++)
            #pragma unroll
            for (int j = 0; j < 4; j++) acc[mi][ni][j] = 0.f;

    float4 pa[4], pb[4];

    auto load_g = [&](int s) {
        int k0 = s * 32;
        #pragma unroll
        for (int i = 0; i < 4; i++) pa[i] = *(const float4*)(arow[i] + k0);
        #pragma unroll
        for (int i = 0; i < 4; i++) pb[i] = *(const float4*)(brow[i] + k0);
    };
    auto store_s = [&](int buf) {
        char* ab = smem + buf * MM_STAGE_BYTES;
        char* bb = ab + 16384;
        #pragma unroll
        for (int i = 0; i < 4; i++)
            *(float4*)(ab + sw + i * (32 * 128)) = pa[i];
        #pragma unroll
        for (int i = 0; i < 4; i++)
            *(float4*)(bb + sw + i * (32 * 128)) = pb[i];
    };
    auto compute = [&](int buf) {
        uint32_t abase = sbase + buf * MM_STAGE_BYTES;
        uint32_t bbs   = abase + 16384;
        #pragma unroll
        for (int ks = 0; ks < 4; ks++) {
            uint32_t af[4][4];
            #pragma unroll
            for (int mi = 0; mi < 4; mi++) {
                uint32_t addr = abase + (uint32_t)((rowa_base + mi * 16) * 128)
                              + ((((uint32_t)(ks * 2 + lhiA)) << 4) ^ aswz);
                asm volatile("ldmatrix.sync.aligned.m8n8.x4.shared.b16 {%0,%1,%2,%3}, [%4];"
                    : "=r"(af[mi][0]), "=r"(af[mi][1]), "=r"(af[mi][2]), "=r"(af[mi][3])
                    : "r"(addr));
            }
            #pragma unroll
            for (int nj = 0; nj < 2; nj++) {
                uint32_t bf0, bf1, bf2, bf3;
                uint32_t addr = bbs + (uint32_t)((rowb2 + nj * 16) * 128)
                              + ((((uint32_t)(ks * 2 + lbB)) << 4) ^ bswz);
                asm volatile("ldmatrix.sync.aligned.m8n8.x4.shared.b16 {%0,%1,%2,%3}, [%4];"
                    : "=r"(bf0), "=r"(bf1), "=r"(bf2), "=r"(bf3) : "r"(addr));
                #pragma unroll
                for (int mi = 0; mi < 4; mi++) {
                    asm volatile("mma.sync.aligned.m16n8k8.row.col.f32.tf32.tf32.f32 "
                        "{%0,%1,%2,%3}, {%4,%5,%6,%7}, {%8,%9}, {%0,%1,%2,%3};"
                        : "+f"(acc[mi][2*nj][0]), "+f"(acc[mi][2*nj][1]),
                          "+f"(acc[mi][2*nj][2]), "+f"(acc[mi][2*nj][3])
                        : "r"(af[mi][0]), "r"(af[mi][1]), "r"(af[mi][2]), "r"(af[mi][3]),
                          "r"(bf0), "r"(bf1));
                    asm volatile("mma.sync.aligned.m16n8k8.row.col.f32.tf32.tf32.f32 "
                        "{%0,%1,%2,%3}, {%4,%5,%6,%7}, {%8,%9}, {%0,%1,%2,%3};"
                        : "+f"(acc[mi][2*nj+1][0]), "+f"(acc[mi][2*nj+1][1]),
                          "+f"(acc[mi][2*nj+1][2]), "+f"(acc[mi][2*nj+1][3])
                        : "r"(af[mi][0]), "r"(af[mi][1]), "r"(af[mi][2]), "r"(af[mi][3]),
                          "r"(bf2), "r"(bf3));
                }
            }
        }
    };

    const int NSTAGE = KDIM / 32;
    load_g(0);
    store_s(0);
    __syncthreads();
    for (int s = 0; s < NSTAGE; ++s) {
        int buf = s & 1;
        if (s + 1 < NSTAGE) load_g(s + 1);
        compute(buf);
        if (s + 1 < NSTAGE) store_s(buf ^ 1);
        __syncthreads();
    }

    // ---- epilogue ----
    int qr = lane >> 2, c2 = (lane & 3) * 2;
    #pragma unroll
    for (int mi = 0; mi < 4; mi++) {
        int r0 = bm + wr * 64 + mi * 16 + qr;
        #pragma unroll
        for (int ni = 0; ni < 4; ni++) {
            int col = bn + wc * 32 + ni * 8 + c2;
            float v0 = acc[mi][ni][0], v1 = acc[mi][ni][1];
            float v2 = acc[mi][ni][2], v3 = acc[mi][ni][3];
            if (MODE == 1) {
                float2 ra = *(const float2*)(aux + (size_t)r0 * NDIM + col);
                float2 rb = *(const float2*)(aux + (size_t)(r0 + 8) * NDIM + col);
                v0 += ra.x; v1 += ra.y; v2 += rb.x; v3 += rb.y;
            }
            if (MODE >= 2) {
                float2 bz = *(const float2*)(bias + col);
                v0 += bz.x; v1 += bz.y; v2 += bz.x; v3 += bz.y;
                if (MODE == 2) {
                    v0 = f2tf_f(gelu_tanh(v0)); v1 = f2tf_f(gelu_tanh(v1));
                    v2 = f2tf_f(gelu_tanh(v2)); v3 = f2tf_f(gelu_tanh(v3));
                }
            }
            *(float2*)(C + (size_t)r0 * NDIM + col)       = make_float2(v0, v1);
            *(float2*)(C + (size_t)(r0 + 8) * NDIM + col) = make_float2(v2, v3);
        }
    }
}

// ---------------- LayerNorm ----------------
// y: tf32-rounded (GEMM operand). If DUAL, y_raw gets the unrounded values (router input).
template<bool DUAL>
__global__ __launch_bounds__(256)
void ln_kernel(const float* __restrict__ x, const float* __restrict__ g,
               const float* __restrict__ b, float* __restrict__ y,
               float* __restrict__ y_raw) {
    int n = blockIdx.x;
    int tid = threadIdx.x;
    const float4* xr = (const float4*)(x + (size_t)n * DD);
    float4 v = xr[tid];
    float s  = v.x + v.y + v.z + v.w;
    float sq = v.x*v.x + v.y*v.y + v.z*v.z + v.w*v.w;
    __shared__ float red[2][8];
    int lane = tid & 31, wid = tid >> 5;
    #pragma unroll
    for (int o = 16; o > 0; o >>= 1) {
        s  += __shfl_down_sync(0xffffffffu, s,  o);
        sq += __shfl_down_sync(0xffffffffu, sq, o);
    }
    if (lane == 0) { red[0][wid] = s; red[1][wid] = sq; }
    __syncthreads();
    if (wid == 0) {
        float a = (lane < 8) ? red[0][lane] : 0.f;
        float c = (lane < 8) ? red[1][lane] : 0.f;
        #pragma unroll
        for (int o = 4; o > 0; o >>= 1) {
            a += __shfl_down_sync(0xffffffffu, a, o);
            c += __shfl_down_sync(0xffffffffu, c, o);
        }
        if (lane == 0) { red[0][0] = a; red[1][0] = c; }
    }
    __syncthreads();
    float mean = red[0][0] * (1.0f / DD);
    float var  = red[1][0] * (1.0f / DD) - mean * mean;
    float rstd = rsqrtf(var + 1e-5f);
    float4 gv = ((const float4*)g)[tid];
    float4 bv = ((const float4*)b)[tid];
    float4 o;
    o.x = (v.x - mean) * rstd * gv.x + bv.x;
    o.y = (v.y - mean) * rstd * gv.y + bv.y;
    o.z = (v.z - mean) * rstd * gv.z + bv.z;
    o.w = (v.w - mean) * rstd * gv.w + bv.w;
    if (DUAL)
        ((float4*)(y_raw + (size_t)n * DD))[tid] = o;
    float4 orn;
    orn.x = f2tf_f(o.x); orn.y = f2tf_f(o.y);
    orn.z = f2tf_f(o.z); orn.w = f2tf_f(o.w);
    ((float4*)(y + (size_t)n * DD))[tid] = orn;
}

// ---------------- causal flash attention (fp32 SIMT; 8-way partial sums) ----------------
__global__ __launch_bounds__(64)
void attn_kernel(const float* __restrict__ qkv, float* __restrict__ o) {
    __shared__ float KV[64][64];
    __shared__ float Sb[64][65];
    int qt = blockIdx.x, h = blockIdx.y, b = blockIdx.z;
    int t = threadIdx.x;
    int q = qt * 64 + t;
    const float* qrow = qkv + (size_t)(b * SS + q) * (3 * DD) + h * 64;
    float qreg[64];
    #pragma unroll
    for (int d = 0; d < 64; d++) qreg[d] = qrow[d];
    float acc[64];
    #pragma unroll
    for (int d = 0; d < 64; d++) acc[d] = 0.f;
    float m = -1e30f, l = 0.f;
    const float scale = 0.125f;
    for (int kt = 0; kt <= qt; ++kt) {
        for (int i = t; i < 1024; i += 64) {
            int j = i * 4; int kk = j >> 6; int d = j & 63;
            *(float4*)&KV[kk][d] = *(const float4*)(
                qkv + (size_t)(b * SS + kt * 64 + kk) * (3 * DD) + DD + h * 64 + d);
        }
        __syncthreads();
        int kmax = (kt == qt) ? (t + 1) : 64;
        float tmax = -1e30f;
        for (int kk = 0; kk < kmax; ++kk) {
            float p0 = 0.f, p1 = 0.f, p2 = 0.f, p3 = 0.f;
            float p4 = 0.f, p5 = 0.f, p6 = 0.f, p7 = 0.f;
            #pragma unroll
            for (int d = 0; d < 64; d += 8) {
                p0 += qreg[d+0] * KV[kk][d+0];
                p1 += qreg[d+1] * KV[kk][d+1];
                p2 += qreg[d+2] * KV[kk][d+2];
                p3 += qreg[d+3] * KV[kk][d+3];
                p4 += qreg[d+4] * KV[kk][d+4];
                p5 += qreg[d+5] * KV[kk][d+5];
                p6 += qreg[d+6] * KV[kk][d+6];
                p7 += qreg[d+7] * KV[kk][d+7];
            }
            float s = (((p0 + p1) + (p2 + p3)) + ((p4 + p5) + (p6 + p7))) * scale;
            Sb[t][kk] = s;
            tmax = fmaxf(tmax, s);
        }
        float mn = fmaxf(m, tmax);
        float corr = __expf(m - mn);
        #pragma unroll
        for (int d = 0; d < 64; d++) acc[d] *= corr;
        l *= corr;
        m = mn;
        __syncthreads();
        for (int i = t; i < 1024; i += 64) {
            int j = i * 4; int kk = j >> 6; int d = j & 63;
            *(float4*)&KV[kk][d] = *(const float4*)(
                qkv + (size_t)(b * SS + kt * 64 + kk) * (3 * DD) + 2 * DD + h * 64 + d);
        }
        __syncthreads();
        for (int kk = 0; kk < kmax; ++kk) {
            float p = __expf(Sb[t][kk] - m);
            l += p;
            #pragma unroll
            for (int d = 0; d < 64; d++) acc[d] += p * KV[kk][d];
        }
        __syncthreads();
    }
    float inv = 1.f / l;
    float* orow = o + (size_t)(b * SS + q) * DD + h * 64;
    #pragma unroll
    for (int d = 0; d < 64; d++) orow[d] = f2tf_f(acc[d] * inv);
}

// ---------------- gate: logits + top-2 (uses UNROUNDED moe input) ----------------
__global__ __launch_bounds__(128)
void gate_kernel(const float* __restrict__ moe_raw, const float* __restrict__ w_gate) {
    int lane = threadIdx.x & 31, wid = threadIdx.x >> 5;
    int n = blockIdx.x * 4 + wid;
    float acc[EE];
    #pragma unroll
    for (int e = 0; e < EE; e++) acc[e] = 0.f;
    const float* xr = moe_raw + (size_t)n * DD;
    for (int d = lane; d < DD; d += 32) {
        float xv = xr[d];
        const float* wg = w_gate + (size_t)d * EE;
        #pragma unroll
        for (int e = 0; e < EE; e++) acc[e] += xv * wg[e];
    }
    #pragma unroll
    for (int e = 0; e < EE; e++) {
        #pragma unroll
        for (int o = 16; o > 0; o >>= 1)
            acc[e] += __shfl_down_sync(0xffffffffu, acc[e], o);
    }
    if (lane == 0) {
        int i0 = 0;
        #pragma unroll
        for (int e = 1; e < EE; e++) if (acc[e] > acc[i0]) i0 = e;
        int i1 = (i0 == 0) ? 1 : 0;
        #pragma unroll
        for (int e = 0; e < EE; e++)
            if (e != i0 && acc[e] > acc[i1]) i1 = e;
        float w0 = 1.f / (1.f + __expf(acc[i1] - acc[i0]));
        g_top_e[2*n]   = i0;  g_top_e[2*n+1]   = i1;
        g_top_w[2*n]   = w0;  g_top_w[2*n+1]   = 1.f - w0;
    }
}

// ---------------- routing ----------------
__global__ void counts_kernel() {
    __shared__ int cnt;
    if (threadIdx.x == 0) cnt = 0;
    __syncthreads();
    int e = blockIdx.x;
    int local = 0;
    for (int n = threadIdx.x; n < NTOK; n += 256)
        if (g_top_e[2*n] == e || g_top_e[2*n+1] == e) local++;
    atomicAdd(&cnt, local);
    __syncthreads();
    if (threadIdx.x == 0) g_counts[e] = cnt;
}

__global__ void offsets_kernel() {
    int off = 0;
    for (int e = 0; e < EE; ++e) {
        g_pad_off[e] = off;
        int seg = ((g_counts[e] + 127) >> 7) << 7;
        int t0 = off >> 7, t1 = (off + seg) >> 7;
        for (int t = t0; t < t1; ++t) g_tile_expert[t] = e;
        off += seg;
    }
    g_pad_off[EE] = off;
    g_n_mtiles = off >> 7;
}

__global__ __launch_bounds__(128)
void compact_kernel() {
    int e = blockIdx.x;
    int tid = threadIdx.x;
    int lane = tid & 31, wid = tid >> 5;
    __shared__ int warp_cnt[4];
    __shared__ int running;
    if (tid == 0) running = 0;
    __syncthreads();
    int base = g_pad_off[e];
    for (int c = 0; c < NTOK / 128; ++c) {
        int n = c * 128 + tid;
        int k = -1;
        if (g_top_e[2*n] == e) k = 0;
        else if (g_top_e[2*n+1] == e) k = 1;
        unsigned msk = __ballot_sync(0xffffffffu, k >= 0);
        int rank = __popc(msk & ((1u << lane) - 1));
        if (lane == 0) warp_cnt[wid] = __popc(msk);
        __syncthreads();
        int wbase = 0;
        #pragma unroll
        for (int w = 0; w < 4; ++w) if (w < wid) wbase += warp_cnt[w];
        int cur = running;
        if (k >= 0) {
            int slot = base + cur + wbase + rank;
            g_tok_of_slot[slot] = n;
            g_slot_of[2*n + k]  = slot;
        }
        __syncthreads();
        if (tid == 0)
            running = cur + warp_cnt[0] + warp_cnt[1] + warp_cnt[2] + warp_cnt[3];
        __syncthreads();
    }
    int cnt = running;
    int end = g_pad_off[e + 1];
    for (int s = base + cnt + tid; s < end; s += 128) g_tok_of_slot[s] = 0;
}

// ---------------- combine ----------------
__global__ __launch_bounds__(256)
void combine_kernel(const float* __restrict__ xres, const float* __restrict__ y,
                    float* __restrict__ out) {
    int n = blockIdx.x;
    int s0 = g_slot_of[2*n], s1 = g_slot_of[2*n+1];
    float wa = g_top_w[2*n], wb = g_top_w[2*n+1];
    int tid = threadIdx.x;
    float4 a  = ((const float4*)(xres + (size_t)n  * DD))[tid];
    float4 y0 = ((const float4*)(y + (size_t)s0 * DD))[tid];
    float4 y1 = ((const float4*)(y + (size_t)s1 * DD))[tid];
    float4 r;
    r.x = a.x + wa * y0.x + wb * y1.x;
    r.y = a.y + wa * y0.y + wb * y1.y;
    r.z = a.z + wa * y0.z + wb * y1.z;
    r.w = a.w + wa * y0.w + wb * y1.w;
    ((float4*)(out + (size_t)n * DD))[tid] = r;
}

// ---------------- launch ----------------
extern "C" void kernel_launch(void* const* d_in, const int* in_sizes, int n_in,
                              void* d_out, int out_size) {
    const float* x      = (const float*)d_in[0];
    const float* ln1_g  = (const float*)d_in[1];
    const float* ln1_b  = (const float*)d_in[2];
    const float* ln2_g  = (const float*)d_in[3];
    const float* ln2_b  = (const float*)d_in[4];
    const float* w_qkv  = (const float*)d_in[5];
    const float* w_o    = (const float*)d_in[6];
    const float* w_gate = (const float*)d_in[7];
    const float* w1     = (const float*)d_in[8];
    const float* b1     = (const float*)d_in[9];
    const float* w2     = (const float*)d_in[10];
    const float* b2     = (const float*)d_in[11];
    float* out = (float*)d_out;

    float* p_hln;  cudaGetSymbolAddress((void**)&p_hln,  g_hln);
    float* p_qkv;  cudaGetSymbolAddress((void**)&p_qkv,  g_qkv);
    float* p_attn; cudaGetSymbolAddress((void**)&p_attn, g_attn);
    float* p_xres; cudaGetSymbolAddress((void**)&p_xres, g_xres);
    float* p_moein;cudaGetSymbolAddress((void**)&p_moein,g_moein);
    float* p_moeraw;cudaGetSymbolAddress((void**)&p_moeraw,g_moeraw);
    float* p_h1;   cudaGetSymbolAddress((void**)&p_h1,   g_h1);
    float* p_y;    cudaGetSymbolAddress((void**)&p_y,    g_y);
    float* p_wqkv; cudaGetSymbolAddress((void**)&p_wqkv, g_wt_qkv);
    float* p_wo;   cudaGetSymbolAddress((void**)&p_wo,   g_wt_o);
    float* p_w1;   cudaGetSymbolAddress((void**)&p_w1,   g_wt1);
    float* p_w2;   cudaGetSymbolAddress((void**)&p_w2,   g_wt2);

    cudaFuncSetAttribute(gemm_mma<0, DD, 3*DD>, cudaFuncAttributeMaxDynamicSharedMemorySize, MM_SMEM_BYTES);
    cudaFuncSetAttribute(gemm_mma<1, DD, DD>,   cudaFuncAttributeMaxDynamicSharedMemorySize, MM_SMEM_BYTES);
    cudaFuncSetAttribute(gemm_mma<2, DD, FF>,   cudaFuncAttributeMaxDynamicSharedMemorySize, MM_SMEM_BYTES);
    cudaFuncSetAttribute(gemm_mma<3, FF, DD>,   cudaFuncAttributeMaxDynamicSharedMemorySize, MM_SMEM_BYTES);

    dim3 tb(32, 8);
    // 0. weight transpose + tf32 round
    transpose_round<<<dim3(3*DD/32, DD/32, 1),  tb>>>(w_qkv, p_wqkv, DD, 3*DD);
    transpose_round<<<dim3(DD/32,   DD/32, 1),  tb>>>(w_o,   p_wo,   DD, DD);
    transpose_round<<<dim3(FF/32,   DD/32, EE), tb>>>(w1,    p_w1,   DD, FF);
    transpose_round<<<dim3(DD/32,   FF/32, EE), tb>>>(w2,    p_w2,   FF, DD);
    // 1. LN1 (rounded only; feeds QKV GEMM)
    ln_kernel<false><<<NTOK, 256>>>(x, ln1_g, ln1_b, p_hln, nullptr);
    // 2. QKV GEMM
    gemm_mma<0, DD, 3*DD><<<dim3(3*DD/128, NTOK/128), 256, MM_SMEM_BYTES>>>(p_hln, p_wqkv, nullptr, p_qkv);
    // 3. causal attention
    attn_kernel<<<dim3(SS/64, HH, BB), 64>>>(p_qkv, p_attn);
    // 4. O-proj + residual
    gemm_mma<1, DD, DD><<<dim3(DD/128, NTOK/128), 256, MM_SMEM_BYTES>>>(p_attn, p_wo, x, p_xres);
    // 5. LN2 (dual: rounded for GEMM, raw for router)
    ln_kernel<true><<<NTOK, 256>>>(p_xres, ln2_g, ln2_b, p_moein, p_moeraw);
    // 6. gate + top-2 on RAW activations
    gate_kernel<<<NTOK/4, 128>>>(p_moeraw, w_gate);
    // 7-9. routing
    counts_kernel<<<EE, 256>>>();
    offsets_kernel<<<1, 1>>>();
    compact_kernel<<<EE, 128>>>();
    // 10. MoE up: gelu(x @ w1[e] + b1[e])
    gemm_mma<2, DD, FF><<<dim3(FF/128, MAXMT), 256, MM_SMEM_BYTES>>>(p_moein, p_w1, b1, p_h1);
    // 11. MoE down: h1 @ w2[e] + b2[e]
    gemm_mma<3, FF, DD><<<dim3(DD/128, MAXMT), 256, MM_SMEM_BYTES>>>(p_h1, p_w2, b2, p_y);
    // 12. combine + residual
    combine_kernel<<<NTOK, 256>>>(p_xres, p_y, out);
}

// round 12
// speedup vs baseline: 1.1746x; 1.1746x over previous
#include <cuda_runtime.h>
#include <cuda_bf16.h>
#include <stdint.h>
#include <math.h>

// Problem constants
#define BB 8
#define SS 512
#define DD 1024
#define FF 4096
#define EE 8
#define HH 16
#define NTOK 4096              // B*S
#define NSLOT 8192             // NTOK * top2
#define MAXPAD 9216            // 8192 + 8*128 padding
#define MAXMT 72               // MAXPAD/128

// ---------------- scratch (device globals; no allocation) ----------------
__device__ float g_hln  [NTOK * DD];
__device__ float g_qkv  [NTOK * 3 * DD];
__device__ float g_attn [NTOK * DD];
__device__ float g_xres [NTOK * DD];
__device__ float g_moein[NTOK * DD];    // tf32-rounded (GEMM A)
__device__ float g_moeraw[NTOK * DD];   // unrounded (gate input)
__device__ float g_h1  [MAXPAD * FF];
__device__ float g_y   [MAXPAD * DD];

// tf32-rounded, transposed (K-major, [N][K]) weights
__device__ float g_wt_qkv[3 * DD * DD];
__device__ float g_wt_o  [DD * DD];
__device__ float g_wt1   [EE * FF * DD];   // per e: [F][D]
__device__ float g_wt2   [EE * DD * FF];   // per e: [D][F]

__device__ int   g_top_e[NSLOT];
__device__ float g_top_w[NSLOT];
__device__ int   g_counts[EE];
__device__ int   g_pad_off[EE + 1];
__device__ int   g_tile_expert[MAXMT];
__device__ int   g_n_mtiles;
__device__ int   g_tok_of_slot[MAXPAD];
__device__ int   g_slot_of[NSLOT];

// ---------------- helpers ----------------
__device__ __forceinline__ uint32_t smem_u32(const void* p) {
    uint32_t a;
    asm("{ .reg .u64 t; cvta.to.shared.u64 t, %1; cvt.u32.u64 %0, t; }" : "=r"(a) : "l"(p));
    return a;
}
__device__ __forceinline__ uint32_t f2tf(float f) {
    uint32_t u;
    asm("cvt.rna.tf32.f32 %0, %1;" : "=r"(u) : "f"(f));
    return u;
}
__device__ __forceinline__ float f2tf_f(float f) { return __uint_as_float(f2tf(f)); }
__device__ __forceinline__ float gelu_tanh(float v) {
    const float c = 0.7978845608028654f;
    float u = c * (v + 0.044715f * v * v * v);
    return 0.5f * v * (1.0f + tanhf(u));
}

// ---------------- weight transpose + tf32 round: src[R][C] -> dst[C][R] ----------------
__global__ __launch_bounds__(256)
void transpose_round(const float* __restrict__ src, float* __restrict__ dst, int R, int C) {
    __shared__ float t[32][33];
    const float* s = src + (size_t)blockIdx.z * R * C;
    float*       d = dst + (size_t)blockIdx.z * R * C;
    int r0 = blockIdx.y * 32, c0 = blockIdx.x * 32;
    int tx = threadIdx.x, ty = threadIdx.y;         // 32 x 8
    #pragma unroll
    for (int i = 0; i < 32; i += 8)
        t[ty + i][tx] = s[(size_t)(r0 + ty + i) * C + c0 + tx];
    __syncthreads();
    #pragma unroll
    for (int i = 0; i < 32; i += 8)
        d[(size_t)(c0 + ty + i) * R + r0 + tx] = f2tf_f(t[tx][ty + i]);
}

// ============ tf32 mma.sync GEMM: 128x256 CTA tile, 256 thr, warp 64x64 (2x4 grid) ============
// MODE 0: C = round(A*B)     MODE 1: C = A*B + aux
// MODE 2: C = gelu(Agather*B+b1), output tf32-rounded
// MODE 3: C = A*B + b2
#define MM_STAGE_BYTES 49152   // 16KB A + 32KB B
#define MM_SMEM_BYTES  98304   // 2 stages

template<int MODE, int KDIM, int NDIM>
__global__ __launch_bounds__(256)
void gemm_mma(const float* __restrict__ A, const float* __restrict__ Wt,
              const float* __restrict__ aux, float* __restrict__ C) {
    int mt = blockIdx.y;
    if (MODE >= 2 && mt >= g_n_mtiles) return;
    const float* Wb = Wt;
    const float* bias = aux;
    if (MODE >= 2) {
        int e = g_tile_expert[mt];
        Wb   = Wt + (size_t)e * KDIM * NDIM;
        bias = aux + (size_t)e * NDIM;
    }
    extern __shared__ __align__(16) char smem[];
    uint32_t sbase = smem_u32(smem);

    int tid = threadIdx.x;
    int lane = tid & 31, wid = tid >> 5;
    int bm = mt * 128, bn = blockIdx.x * 256;

    int rg = tid >> 3, cc = tid & 7;
    const float* arow[4];
    #pragma unroll
    for (int i = 0; i < 4; i++) {
        int r = rg + i * 32;
        int m = (MODE == 2) ? g_tok_of_slot[bm + r] : (bm + r);
        arow[i] = A + (size_t)m * KDIM + cc * 4;
    }
    const float* bbase = Wb + (size_t)(bn + rg) * KDIM + cc * 4;
    uint32_t sw = (uint32_t)(((cc ^ (rg & 7)) << 4) + rg * 128);

    int wr = wid & 1, wc = wid >> 1;
    int rowa_base = wr * 64 + (lane & 7) + ((lane >> 3) & 1) * 8;
    int lhiA = lane >> 4;
    uint32_t aswz = (uint32_t)((rowa_base & 7) << 4);
    int rowb2 = wc * 64 + (lane & 7) + ((lane >> 4) & 1) * 8;
    int lbB = (lane >> 3) & 1;
    uint32_t bswz = (uint32_t)((lane & 7) << 4);

    float acc[4][8][4];
    #pragma unroll
    for (int mi = 0; mi < 4; mi++)
        #pragma unroll
        for (int ni = 0; ni < 8; ni++)
            #pragma unroll
            for (int j = 0; j < 4; j++) acc[mi][ni][j] = 0.f;

    float4 pa[4], pb[8];

    auto load_g = [&](int s) {
        int k0 = s * 32;
        #pragma unroll
        for (int i = 0; i < 4; i++) pa[i] = *(const float4*)(arow[i] + k0);
        #pragma unroll
        for (int i = 0; i < 8; i++)
            pb[i] = *(const float4*)(bbase + k0 + (size_t)i * 32 * KDIM);
    };
    auto store_s = [&](int buf) {
        char* ab = smem + buf * MM_STAGE_BYTES;
        char* bb = ab + 16384;
        #pragma unroll
        for (int i = 0; i < 4; i++)
            *(float4*)(ab + sw + i * (32 * 128)) = pa[i];
        #pragma unroll
        for (int i = 0; i < 8; i++)
            *(float4*)(bb + sw + i * (32 * 128)) = pb[i];
    };
    auto compute = [&](int buf) {
        uint32_t abase = sbase + buf * MM_STAGE_BYTES;
        uint32_t bbs   = abase + 16384;
        #pragma unroll
        for (int ks = 0; ks < 4; ks++) {
            uint32_t af[4][4];
            #pragma unroll
            for (int mi = 0; mi < 4; mi++) {
                uint32_t addr = abase + (uint32_t)((rowa_base + mi * 16) * 128)
                              + ((((uint32_t)(ks * 2 + lhiA)) << 4) ^ aswz);
                asm volatile("ldmatrix.sync.aligned.m8n8.x4.shared.b16 {%0,%1,%2,%3}, [%4];"
                    : "=r"(af[mi][0]), "=r"(af[mi][1]), "=r"(af[mi][2]), "=r"(af[mi][3])
                    : "r"(addr));
            }
            #pragma unroll
            for (int nj = 0; nj < 4; nj++) {
                uint32_t bf0, bf1, bf2, bf3;
                uint32_t addr = bbs + (uint32_t)((rowb2 + nj * 16) * 128)
                              + ((((uint32_t)(ks * 2 + lbB)) << 4) ^ bswz);
                asm volatile("ldmatrix.sync.aligned.m8n8.x4.shared.b16 {%0,%1,%2,%3}, [%4];"
                    : "=r"(bf0), "=r"(bf1), "=r"(bf2), "=r"(bf3) : "r"(addr));
                #pragma unroll
                for (int mi = 0; mi < 4; mi++) {
                    asm volatile("mma.sync.aligned.m16n8k8.row.col.f32.tf32.tf32.f32 "
                        "{%0,%1,%2,%3}, {%4,%5,%6,%7}, {%8,%9}, {%0,%1,%2,%3};"
                        : "+f"(acc[mi][2*nj][0]), "+f"(acc[mi][2*nj][1]),
                          "+f"(acc[mi][2*nj][2]), "+f"(acc[mi][2*nj][3])
                        : "r"(af[mi][0]), "r"(af[mi][1]), "r"(af[mi][2]), "r"(af[mi][3]),
                          "r"(bf0), "r"(bf1));
                    asm volatile("mma.sync.aligned.m16n8k8.row.col.f32.tf32.tf32.f32 "
                        "{%0,%1,%2,%3}, {%4,%5,%6,%7}, {%8,%9}, {%0,%1,%2,%3};"
                        : "+f"(acc[mi][2*nj+1][0]), "+f"(acc[mi][2*nj+1][1]),
                          "+f"(acc[mi][2*nj+1][2]), "+f"(acc[mi][2*nj+1][3])
                        : "r"(af[mi][0]), "r"(af[mi][1]), "r"(af[mi][2]), "r"(af[mi][3]),
                          "r"(bf2), "r"(bf3));
                }
            }
        }
    };

    const int NSTAGE = KDIM / 32;
    load_g(0);
    store_s(0);
    __syncthreads();
    for (int s = 0; s < NSTAGE; ++s) {
        int buf = s & 1;
        if (s + 1 < NSTAGE) load_g(s + 1);
        compute(buf);
        if (s + 1 < NSTAGE) store_s(buf ^ 1);
        __syncthreads();
    }

    int qr = lane >> 2, c2 = (lane & 3) * 2;
    #pragma unroll
    for (int mi = 0; mi < 4; mi++) {
        int r0 = bm + wr * 64 + mi * 16 + qr;
        #pragma unroll
        for (int ni = 0; ni < 8; ni++) {
            int col = bn + wc * 64 + ni * 8 + c2;
            float v0 = acc[mi][ni][0], v1 = acc[mi][ni][1];
            float v2 = acc[mi][ni][2], v3 = acc[mi][ni][3];
            if (MODE == 0) {
                v0 = f2tf_f(v0); v1 = f2tf_f(v1); v2 = f2tf_f(v2); v3 = f2tf_f(v3);
            }
            if (MODE == 1) {
                float2 ra = *(const float2*)(aux + (size_t)r0 * NDIM + col);
                float2 rb = *(const float2*)(aux + (size_t)(r0 + 8) * NDIM + col);
                v0 += ra.x; v1 += ra.y; v2 += rb.x; v3 += rb.y;
            }
            if (MODE >= 2) {
                float2 bz = *(const float2*)(bias + col);
                v0 += bz.x; v1 += bz.y; v2 += bz.x; v3 += bz.y;
                if (MODE == 2) {
                    v0 = f2tf_f(gelu_tanh(v0)); v1 = f2tf_f(gelu_tanh(v1));
                    v2 = f2tf_f(gelu_tanh(v2)); v3 = f2tf_f(gelu_tanh(v3));
                }
            }
            *(float2*)(C + (size_t)r0 * NDIM + col)       = make_float2(v0, v1);
            *(float2*)(C + (size_t)(r0 + 8) * NDIM + col) = make_float2(v2, v3);
        }
    }
}

// ---------------- LayerNorm ----------------
template<bool DUAL>
__global__ __launch_bounds__(256)
void ln_kernel(const float* __restrict__ x, const float* __restrict__ g,
               const float* __restrict__ b, float* __restrict__ y,
               float* __restrict__ y_raw) {
    int n = blockIdx.x;
    int tid = threadIdx.x;
    const float4* xr = (const float4*)(x + (size_t)n * DD);
    float4 v = xr[tid];
    float s  = v.x + v.y + v.z + v.w;
    float sq = v.x*v.x + v.y*v.y + v.z*v.z + v.w*v.w;
    __shared__ float red[2][8];
    int lane = tid & 31, wid = tid >> 5;
    #pragma unroll
    for (int o = 16; o > 0; o >>= 1) {
        s  += __shfl_down_sync(0xffffffffu, s,  o);
        sq += __shfl_down_sync(0xffffffffu, sq, o);
    }
    if (lane == 0) { red[0][wid] = s; red[1][wid] = sq; }
    __syncthreads();
    if (wid == 0) {
        float a = (lane < 8) ? red[0][lane] : 0.f;
        float c = (lane < 8) ? red[1][lane] : 0.f;
        #pragma unroll
        for (int o = 4; o > 0; o >>= 1) {
            a += __shfl_down_sync(0xffffffffu, a, o);
            c += __shfl_down_sync(0xffffffffu, c, o);
        }
        if (lane == 0) { red[0][0] = a; red[1][0] = c; }
    }
    __syncthreads();
    float mean = red[0][0] * (1.0f / DD);
    float var  = red[1][0] * (1.0f / DD) - mean * mean;
    float rstd = rsqrtf(var + 1e-5f);
    float4 gv = ((const float4*)g)[tid];
    float4 bv = ((const float4*)b)[tid];
    float4 o;
    o.x = (v.x - mean) * rstd * gv.x + bv.x;
    o.y = (v.y - mean) * rstd * gv.y + bv.y;
    o.z = (v.z - mean) * rstd * gv.z + bv.z;
    o.w = (v.w - mean) * rstd * gv.w + bv.w;
    if (DUAL)
        ((float4*)(y_raw + (size_t)n * DD))[tid] = o;
    float4 orn;
    orn.x = f2tf_f(o.x); orn.y = f2tf_f(o.y);
    orn.z = f2tf_f(o.z); orn.w = f2tf_f(o.w);
    ((float4*)(y + (size_t)n * DD))[tid] = orn;
}

// ---------------- causal flash attention (tf32 mma.sync) ----------------
// Block: (qt, h, b), 128 threads (4 warps). Q/K/V tiles 64x64.
// smem: Q@0 (16K), K@16K, V^T@32K, P@48K (4K per warp). Total 64KB.
#define AT_SMEM_BYTES 65536

__global__ __launch_bounds__(128)
void attn_mma_kernel(const float* __restrict__ qkv, float* __restrict__ o) {
    extern __shared__ __align__(16) char smem[];
    uint32_t sbase = smem_u32(smem);
    const int Qo = 0, Ko = 16384, Vo = 32768, Po = 49152;
    int qt = blockIdx.x, h = blockIdx.y, b = blockIdx.z;
    int tid = threadIdx.x, lane = tid & 31, wm = tid >> 5;

    int fr = tid >> 1;              // fill row 0..63
    int fc0 = (tid & 1) * 8;        // float4-chunk base for Q/K fills

    // Q fill (once); values already tf32-rounded by QKV epilogue
    {
        const float* qr_ = qkv + (size_t)(b * SS + qt * 64 + fr) * (3 * DD) + h * 64;
        #pragma unroll
        for (int i = 0; i < 8; i++) {
            int cc = fc0 + i;
            float4 v = *(const float4*)(qr_ + cc * 4);
            *(float4*)(smem + Qo + (cc >> 3) * 8192 + fr * 128 + (((cc & 7) ^ (fr & 7)) << 4)) = v;
        }
    }

    int qr = lane >> 2, lam = lane & 3;
    int rowa = (lane & 7) + ((lane >> 3) & 1) * 8;
    int lhiA = lane >> 4;
    uint32_t aswz = (uint32_t)((rowa & 7) << 4);
    int rowb2 = (lane & 7) + ((lane >> 4) & 1) * 8;
    int lbB = (lane >> 3) & 1;
    uint32_t bswz = (uint32_t)((lane & 7) << 4);

    float acc_o[8][4];
    #pragma unroll
    for (int ni = 0; ni < 8; ni++)
        #pragma unroll
        for (int j = 0; j < 4; j++) acc_o[ni][j] = 0.f;
    float m0 = -1e30f, m1 = -1e30f, l0 = 0.f, l1 = 0.f;

    for (int kt = 0; kt <= qt; ++kt) {
        // K tile fill (K-major rows = keys)
        {
            const float* kr_ = qkv + (size_t)(b * SS + kt * 64 + fr) * (3 * DD) + DD + h * 64;
            #pragma unroll
            for (int i = 0; i < 8; i++) {
                int cc = fc0 + i;
                float4 v = *(const float4*)(kr_ + cc * 4);
                *(float4*)(smem + Ko + (cc >> 3) * 8192 + fr * 128 + (((cc & 7) ^ (fr & 7)) << 4)) = v;
            }
        }
        // V^T fill: read V[key][d] float4, scatter to [d][key]
        {
            const float* vr_ = qkv + (size_t)(b * SS + kt * 64 + fr) * (3 * DD) + 2 * DD + h * 64;
            #pragma unroll
            for (int i = 0; i < 8; i++) {
                int d0 = (tid & 1) * 32 + i * 4;
                float4 v = *(const float4*)(vr_ + d0);
                float vv[4] = {v.x, v.y, v.z, v.w};
                #pragma unroll
                for (int j = 0; j < 4; j++) {
                    int dd = d0 + j;
                    *(float*)(smem + Vo + (fr >> 5) * 8192 + dd * 128
                              + ((((fr & 31) >> 2) ^ (dd & 7)) << 4) + (fr & 3) * 4) = vv[j];
                }
            }
        }
        __syncthreads();

        // ---- S = Q * K^T (warp: rows [wm*16, wm*16+16) x 64 keys) ----
        float accs[8][4];
        #pragma unroll
        for (int ni = 0; ni < 8; ni++)
            #pragma unroll
            for (int j = 0; j < 4; j++) accs[ni][j] = 0.f;
        #pragma unroll
        for (int ks = 0; ks < 8; ks++) {
            uint32_t a0, a1, a2, a3;
            uint32_t aad = sbase + Qo + (ks >> 2) * 8192 + (wm * 16 + rowa) * 128
                         + ((((uint32_t)((ks & 3) * 2 + lhiA)) << 4) ^ aswz);
            asm volatile("ldmatrix.sync.aligned.m8n8.x4.shared.b16 {%0,%1,%2,%3}, [%4];"
                : "=r"(a0), "=r"(a1), "=r"(a2), "=r"(a3) : "r"(aad));
            #pragma unroll
            for (int nj = 0; nj < 4; nj++) {
                uint32_t bf0, bf1, bf2, bf3;
                uint32_t bad = sbase + Ko + (ks >> 2) * 8192 + (rowb2 + nj * 16) * 128
                             + ((((uint32_t)((ks & 3) * 2 + lbB)) << 4) ^ bswz);
                asm volatile("ldmatrix.sync.aligned.m8n8.x4.shared.b16 {%0,%1,%2,%3}, [%4];"
                    : "=r"(bf0), "=r"(bf1), "=r"(bf2), "=r"(bf3) : "r"(bad));
                asm volatile("mma.sync.aligned.m16n8k8.row.col.f32.tf32.tf32.f32 "
                    "{%0,%1,%2,%3}, {%4,%5,%6,%7}, {%8,%9}, {%0,%1,%2,%3};"
                    : "+f"(accs[2*nj][0]), "+f"(accs[2*nj][1]),
                      "+f"(accs[2*nj][2]), "+f"(accs[2*nj][3])
                    : "r"(a0), "r"(a1), "r"(a2), "r"(a3), "r"(bf0), "r"(bf1));
                asm volatile("mma.sync.aligned.m16n8k8.row.col.f32.tf32.tf32.f32 "
                    "{%0,%1,%2,%3}, {%4,%5,%6,%7}, {%8,%9}, {%0,%1,%2,%3};"
                    : "+f"(accs[2*nj+1][0]), "+f"(accs[2*nj+1][1]),
                      "+f"(accs[2*nj+1][2]), "+f"(accs[2*nj+1][3])
                    : "r"(a0), "r"(a1), "r"(a2), "r"(a3), "r"(bf2), "r"(bf3));
            }
        }

        // ---- scale + causal mask + online softmax (rows qr / qr+8 of this warp) ----
        float tm0 = -1e30f, tm1 = -1e30f;
        #pragma unroll
        for (int ni = 0; ni < 8; ni++) {
            #pragma unroll
            for (int j = 0; j < 4; j++) {
                float s = accs[ni][j] * 0.125f;
                int col = ni * 8 + 2 * lam + (j & 1);
                int rl  = wm * 16 + qr + (j >> 1) * 8;
                if (kt == qt && col > rl) s = -1e30f;
                accs[ni][j] = s;
                if ((j >> 1) == 0) tm0 = fmaxf(tm0, s);
                else               tm1 = fmaxf(tm1, s);
            }
        }
        tm0 = fmaxf(tm0, __shfl_xor_sync(0xffffffffu, tm0, 1));
        tm0 = fmaxf(tm0, __shfl_xor_sync(0xffffffffu, tm0, 2));
        tm1 = fmaxf(tm1, __shfl_xor_sync(0xffffffffu, tm1, 1));
        tm1 = fmaxf(tm1, __shfl_xor_sync(0xffffffffu, tm1, 2));
        float mn0 = fmaxf(m0, tm0), mn1 = fmaxf(m1, tm1);
        float c0 = __expf(m0 - mn0), c1 = __expf(m1 - mn1);
        m0 = mn0; m1 = mn1;

        char* pw = smem + Po + wm * 4096;
        float ls0 = 0.f, ls1 = 0.f;
        #pragma unroll
        for (int ni = 0; ni < 8; ni++) {
            #pragma unroll
            for (int j = 0; j < 4; j++) {
                float mrow = (j >> 1) ? m1 : m0;
                float p = f2tf_f(__expf(accs[ni][j] - mrow));
                if (j >> 1) ls1 += p; else ls0 += p;
                int col = ni * 8 + 2 * lam + (j & 1);
                int r   = qr + (j >> 1) * 8;
                *(float*)(pw + (col >> 5) * 2048 + r * 128
                          + ((((col & 31) >> 2) ^ (r & 7)) << 4) + (col & 3) * 4) = p;
            }
        }
        ls0 += __shfl_xor_sync(0xffffffffu, ls0, 1);
        ls0 += __shfl_xor_sync(0xffffffffu, ls0, 2);
        ls1 += __shfl_xor_sync(0xffffffffu, ls1, 1);
        ls1 += __shfl_xor_sync(0xffffffffu, ls1, 2);
        l0 = l0 * c0 + ls0;
        l1 = l1 * c1 + ls1;
        #pragma unroll
        for (int ni = 0; ni < 8; ni++) {
            acc_o[ni][0] *= c0; acc_o[ni][1] *= c0;
            acc_o[ni][2] *= c1; acc_o[ni][3] *= c1;
        }
        __syncwarp();

        // ---- O += P * V (k-dim = 64 keys) ----
        uint32_t pwb = sbase + Po + wm * 4096;
        #pragma unroll
        for (int ks = 0; ks < 8; ks++) {
            uint32_t a0, a1, a2, a3;
            uint32_t aad = pwb + (ks >> 2) * 2048 + rowa * 128
                         + ((((uint32_t)((ks & 3) * 2 + lhiA)) << 4) ^ aswz);
            asm volatile("ldmatrix.sync.aligned.m8n8.x4.shared.b16 {%0,%1,%2,%3}, [%4];"
                : "=r"(a0), "=r"(a1), "=r"(a2), "=r"(a3) : "r"(aad));
            #pragma unroll
            for (int nj = 0; nj < 4; nj++) {
                uint32_t bf0, bf1, bf2, bf3;
                uint32_t bad = sbase + Vo + (ks >> 2) * 8192 + (rowb2 + nj * 16) * 128
                             + ((((uint32_t)((ks & 3) * 2 + lbB)) << 4) ^ bswz);
                asm volatile("ldmatrix.sync.aligned.m8n8.x4.shared.b16 {%0,%1,%2,%3}, [%4];"
                    : "=r"(bf0), "=r"(bf1), "=r"(bf2), "=r"(bf3) : "r"(bad));
                asm volatile("mma.sync.aligned.m16n8k8.row.col.f32.tf32.tf32.f32 "
                    "{%0,%1,%2,%3}, {%4,%5,%6,%7}, {%8,%9}, {%0,%1,%2,%3};"
                    : "+f"(acc_o[2*nj][0]), "+f"(acc_o[2*nj][1]),
                      "+f"(acc_o[2*nj][2]), "+f"(acc_o[2*nj][3])
                    : "r"(a0), "r"(a1), "r"(a2), "r"(a3), "r"(bf0), "r"(bf1));
                asm volatile("mma.sync.aligned.m16n8k8.row.col.f32.tf32.tf32.f32 "
                    "{%0,%1,%2,%3}, {%4,%5,%6,%7}, {%8,%9}, {%0,%1,%2,%3};"
                    : "+f"(acc_o[2*nj+1][0]), "+f"(acc_o[2*nj+1][1]),
                      "+f"(acc_o[2*nj+1][2]), "+f"(acc_o[2*nj+1][3])
                    : "r"(a0), "r"(a1), "r"(a2), "r"(a3), "r"(bf2), "r"(bf3));
            }
        }
        __syncthreads();
    }

    // ---- epilogue: O /= l, write tf32-rounded ----
    float i0 = 1.f / l0, i1 = 1.f / l1;
    int r0 = b * SS + qt * 64 + wm * 16 + qr;
    #pragma unroll
    for (int ni = 0; ni < 8; ni++) {
        int col = h * 64 + ni * 8 + 2 * lam;
        float2 w0 = make_float2(f2tf_f(acc_o[ni][0] * i0), f2tf_f(acc_o[ni][1] * i0));
        float2 w1 = make_float2(f2tf_f(acc_o[ni][2] * i1), f2tf_f(acc_o[ni][3] * i1));
        *(float2*)(o + (size_t)r0 * DD + col)       = w0;
        *(float2*)(o + (size_t)(r0 + 8) * DD + col) = w1;
    }
}

// ---------------- gate: logits + top-2 (uses UNROUNDED moe input) ----------------
__global__ __launch_bounds__(128)
void gate_kernel(const float* __restrict__ moe_raw, const float* __restrict__ w_gate) {
    int lane = threadIdx.x & 31, wid = threadIdx.x >> 5;
    int n = blockIdx.x * 4 + wid;
    float acc[EE];
    #pragma unroll
    for (int e = 0; e < EE; e++) acc[e] = 0.f;
    const float* xr = moe_raw + (size_t)n * DD;
    for (int d = lane; d < DD; d += 32) {
        float xv = xr[d];
        const float* wg = w_gate + (size_t)d * EE;
        #pragma unroll
        for (int e = 0; e < EE; e++) acc[e] += xv * wg[e];
    }
    #pragma unroll
    for (int e = 0; e < EE; e++) {
        #pragma unroll
        for (int o = 16; o > 0; o >>= 1)
            acc[e] += __shfl_down_sync(0xffffffffu, acc[e], o);
    }
    if (lane == 0) {
        int i0 = 0;
        #pragma unroll
        for (int e = 1; e < EE; e++) if (acc[e] > acc[i0]) i0 = e;
        int i1 = (i0 == 0) ? 1 : 0;
        #pragma unroll
        for (int e = 0; e < EE; e++)
            if (e != i0 && acc[e] > acc[i1]) i1 = e;
        float w0 = 1.f / (1.f + __expf(acc[i1] - acc[i0]));
        g_top_e[2*n]   = i0;  g_top_e[2*n+1]   = i1;
        g_top_w[2*n]   = w0;  g_top_w[2*n+1]   = 1.f - w0;
    }
}

// ---------------- routing ----------------
__global__ void counts_kernel() {
    __shared__ int cnt;
    if (threadIdx.x == 0) cnt = 0;
    __syncthreads();
    int e = blockIdx.x;
    int local = 0;
    for (int n = threadIdx.x; n < NTOK; n += 256)
        if (g_top_e[2*n] == e || g_top_e[2*n+1] == e) local++;
    atomicAdd(&cnt, local);
    __syncthreads();
    if (threadIdx.x == 0) g_counts[e] = cnt;
}

__global__ void offsets_kernel() {
    int off = 0;
    for (int e = 0; e < EE; ++e) {
        g_pad_off[e] = off;
        int seg = ((g_counts[e] + 127) >> 7) << 7;
        int t0 = off >> 7, t1 = (off + seg) >> 7;
        for (int t = t0; t < t1; ++t) g_tile_expert[t] = e;
        off += seg;
    }
    g_pad_off[EE] = off;
    g_n_mtiles = off >> 7;
}

__global__ __launch_bounds__(128)
void compact_kernel() {
    int e = blockIdx.x;
    int tid = threadIdx.x;
    int lane = tid & 31, wid = tid >> 5;
    __shared__ int warp_cnt[4];
    __shared__ int running;
    if (tid == 0) running = 0;
    __syncthreads();
    int base = g_pad_off[e];
    for (int c = 0; c < NTOK / 128; ++c) {
        int n = c * 128 + tid;
        int k = -1;
        if (g_top_e[2*n] == e) k = 0;
        else if (g_top_e[2*n+1] == e) k = 1;
        unsigned msk = __ballot_sync(0xffffffffu, k >= 0);
        int rank = __popc(msk & ((1u << lane) - 1));
        if (lane == 0) warp_cnt[wid] = __popc(msk);
        __syncthreads();
        int wbase = 0;
        #pragma unroll
        for (int w = 0; w < 4; ++w) if (w < wid) wbase += warp_cnt[w];
        int cur = running;
        if (k >= 0) {
            int slot = base + cur + wbase + rank;
            g_tok_of_slot[slot] = n;
            g_slot_of[2*n + k]  = slot;
        }
        __syncthreads();
        if (tid == 0)
            running = cur + warp_cnt[0] + warp_cnt[1] + warp_cnt[2] + warp_cnt[3];
        __syncthreads();
    }
    int cnt = running;
    int end = g_pad_off[e + 1];
    for (int s = base + cnt + tid; s < end; s += 128) g_tok_of_slot[s] = 0;
}

// ---------------- combine ----------------
__global__ __launch_bounds__(256)
void combine_kernel(const float* __restrict__ xres, const float* __restrict__ y,
                    float* __restrict__ out) {
    int n = blockIdx.x;
    int s0 = g_slot_of[2*n], s1 = g_slot_of[2*n+1];
    float wa = g_top_w[2*n], wb = g_top_w[2*n+1];
    int tid = threadIdx.x;
    float4 a  = ((const float4*)(xres + (size_t)n  * DD))[tid];
    float4 y0 = ((const float4*)(y + (size_t)s0 * DD))[tid];
    float4 y1 = ((const float4*)(y + (size_t)s1 * DD))[tid];
    float4 r;
    r.x = a.x + wa * y0.x + wb * y1.x;
    r.y = a.y + wa * y0.y + wb * y1.y;
    r.z = a.z + wa * y0.z + wb * y1.z;
    r.w = a.w + wa * y0.w + wb * y1.w;
    ((float4*)(out + (size_t)n * DD))[tid] = r;
}

// ---------------- launch ----------------
extern "C" void kernel_launch(void* const* d_in, const int* in_sizes, int n_in,
                              void* d_out, int out_size) {
    const float* x      = (const float*)d_in[0];
    const float* ln1_g  = (const float*)d_in[1];
    const float* ln1_b  = (const float*)d_in[2];
    const float* ln2_g  = (const float*)d_in[3];
    const float* ln2_b  = (const float*)d_in[4];
    const float* w_qkv  = (const float*)d_in[5];
    const float* w_o    = (const float*)d_in[6];
    const float* w_gate = (const float*)d_in[7];
    const float* w1     = (const float*)d_in[8];
    const float* b1     = (const float*)d_in[9];
    const float* w2     = (const float*)d_in[10];
    const float* b2     = (const float*)d_in[11];
    float* out = (float*)d_out;

    float* p_hln;  cudaGetSymbolAddress((void**)&p_hln,  g_hln);
    float* p_qkv;  cudaGetSymbolAddress((void**)&p_qkv,  g_qkv);
    float* p_attn; cudaGetSymbolAddress((void**)&p_attn, g_attn);
    float* p_xres; cudaGetSymbolAddress((void**)&p_xres, g_xres);
    float* p_moein;cudaGetSymbolAddress((void**)&p_moein,g_moein);
    float* p_moeraw;cudaGetSymbolAddress((void**)&p_moeraw,g_moeraw);
    float* p_h1;   cudaGetSymbolAddress((void**)&p_h1,   g_h1);
    float* p_y;    cudaGetSymbolAddress((void**)&p_y,    g_y);
    float* p_wqkv; cudaGetSymbolAddress((void**)&p_wqkv, g_wt_qkv);
    float* p_wo;   cudaGetSymbolAddress((void**)&p_wo,   g_wt_o);
    float* p_w1;   cudaGetSymbolAddress((void**)&p_w1,   g_wt1);
    float* p_w2;   cudaGetSymbolAddress((void**)&p_w2,   g_wt2);

    cudaFuncSetAttribute(gemm_mma<0, DD, 3*DD>, cudaFuncAttributeMaxDynamicSharedMemorySize, MM_SMEM_BYTES);
    cudaFuncSetAttribute(gemm_mma<1, DD, DD>,   cudaFuncAttributeMaxDynamicSharedMemorySize, MM_SMEM_BYTES);
    cudaFuncSetAttribute(gemm_mma<2, DD, FF>,   cudaFuncAttributeMaxDynamicSharedMemorySize, MM_SMEM_BYTES);
    cudaFuncSetAttribute(gemm_mma<3, FF, DD>,   cudaFuncAttributeMaxDynamicSharedMemorySize, MM_SMEM_BYTES);
    cudaFuncSetAttribute(attn_mma_kernel,       cudaFuncAttributeMaxDynamicSharedMemorySize, AT_SMEM_BYTES);

    dim3 tb(32, 8);
    // 0. weight transpose + tf32 round
    transpose_round<<<dim3(3*DD/32, DD/32, 1),  tb>>>(w_qkv, p_wqkv, DD, 3*DD);
    transpose_round<<<dim3(DD/32,   DD/32, 1),  tb>>>(w_o,   p_wo,   DD, DD);
    transpose_round<<<dim3(FF/32,   DD/32, EE), tb>>>(w1,    p_w1,   DD, FF);
    transpose_round<<<dim3(DD/32,   FF/32, EE), tb>>>(w2,    p_w2,   FF, DD);
    // 1. LN1
    ln_kernel<false><<<NTOK, 256>>>(x, ln1_g, ln1_b, p_hln, nullptr);
    // 2. QKV GEMM (outputs tf32-rounded)
    gemm_mma<0, DD, 3*DD><<<dim3(3*DD/256, NTOK/128), 256, MM_SMEM_BYTES>>>(p_hln, p_wqkv, nullptr, p_qkv);
    // 3. causal attention (tf32 tensor cores)
    attn_mma_kernel<<<dim3(SS/64, HH, BB), 128, AT_SMEM_BYTES>>>(p_qkv, p_attn);
    // 4. O-proj + residual
    gemm_mma<1, DD, DD><<<dim3(DD/256, NTOK/128), 256, MM_SMEM_BYTES>>>(p_attn, p_wo, x, p_xres);
    // 5. LN2 (dual: rounded for GEMM, raw for router)
    ln_kernel<true><<<NTOK, 256>>>(p_xres, ln2_g, ln2_b, p_moein, p_moeraw);
    // 6. gate + top-2 on RAW activations
    gate_kernel<<<NTOK/4, 128>>>(p_moeraw, w_gate);
    // 7-9. routing
    counts_kernel<<<EE, 256>>>();
    offsets_kernel<<<1, 1>>>();
    compact_kernel<<<EE, 128>>>();
    // 10. MoE up: gelu(x @ w1[e] + b1[e])
    gemm_mma<2, DD, FF><<<dim3(FF/256, MAXMT), 256, MM_SMEM_BYTES>>>(p_moein, p_w1, b1, p_h1);
    // 11. MoE down: h1 @ w2[e] + b2[e]
    gemm_mma<3, FF, DD><<<dim3(DD/256, MAXMT), 256, MM_SMEM_BYTES>>>(p_h1, p_w2, b2, p_y);
    // 12. combine + residual
    combine_kernel<<<NTOK, 256>>>(p_xres, p_y, out);
}

// round 13
// speedup vs baseline: 2.0327x; 1.7305x over previous
#include <cuda_runtime.h>
#include <cuda_fp16.h>
#include <stdint.h>
#include <math.h>

// Problem constants
#define BB 8
#define SS 512
#define DD 1024
#define FF 4096
#define EE 8
#define HH 16
#define NTOK 4096              // B*S
#define NSLOT 8192             // NTOK * top2
#define MAXPAD 9216            // 8192 + 8*128 padding
#define MAXMT 72               // MAXPAD/128

// ---------------- scratch (device globals; no allocation) ----------------
__device__ __half g_hln  [NTOK * DD];
__device__ __half g_qkv  [NTOK * 3 * DD];
__device__ __half g_attn [NTOK * DD];
__device__ float  g_xres [NTOK * DD];
__device__ __half g_moein[NTOK * DD];    // fp16 (GEMM A)
__device__ float  g_moeraw[NTOK * DD];   // unrounded (gate input)
__device__ __half g_h1  [MAXPAD * FF];
__device__ float  g_y   [MAXPAD * DD];

// fp16, transposed (K-major, [N][K]) weights
__device__ __half g_wt_qkv[3 * DD * DD];
__device__ __half g_wt_o  [DD * DD];
__device__ __half g_wt1   [EE * FF * DD];   // per e: [F][D]
__device__ __half g_wt2   [EE * DD * FF];   // per e: [D][F]

__device__ int   g_top_e[NSLOT];
__device__ float g_top_w[NSLOT];
__device__ int   g_counts[EE];
__device__ int   g_pad_off[EE + 1];
__device__ int   g_tile_expert[MAXMT];
__device__ int   g_n_mtiles;
__device__ int   g_tok_of_slot[MAXPAD];
__device__ int   g_slot_of[NSLOT];

// ---------------- helpers ----------------
__device__ __forceinline__ uint32_t smem_u32(const void* p) {
    uint32_t a;
    asm("{ .reg .u64 t; cvta.to.shared.u64 t, %1; cvt.u32.u64 %0, t; }" : "=r"(a) : "l"(p));
    return a;
}
__device__ __forceinline__ float gelu_tanh(float v) {
    const float c = 0.7978845608028654f;
    float u = c * (v + 0.044715f * v * v * v);
    return 0.5f * v * (1.0f + tanhf(u));
}

// ---------------- weight transpose + fp16 convert: src[R][C] -> dst[C][R] ----------------
__global__ __launch_bounds__(256)
void transpose_round(const float* __restrict__ src, __half* __restrict__ dst, int R, int C) {
    __shared__ float t[32][33];
    const float* s = src + (size_t)blockIdx.z * R * C;
    __half*      d = dst + (size_t)blockIdx.z * R * C;
    int r0 = blockIdx.y * 32, c0 = blockIdx.x * 32;
    int tx = threadIdx.x, ty = threadIdx.y;         // 32 x 8
    #pragma unroll
    for (int i = 0; i < 32; i += 8)
        t[ty + i][tx] = s[(size_t)(r0 + ty + i) * C + c0 + tx];
    __syncthreads();
    #pragma unroll
    for (int i = 0; i < 32; i += 8)
        d[(size_t)(c0 + ty + i) * R + r0 + tx] = __float2half_rn(t[tx][ty + i]);
}

// ============ fp16 mma.sync GEMM: 128x256 CTA tile, 256 thr, warp 64x64 (2x4 grid) ============
// A and Wt are fp16; Wt is K-major [N][K]. Stage = K-chunk of 64 halves (128 B/row).
// MODE 0: Ch = half(A*B)          MODE 1: Cf = A*B + aux(resid f32)
// MODE 2: Ch = half(gelu(Agather*B+b1))   MODE 3: Cf = A*B + b2
#define MM_STAGE_BYTES 49152   // 16KB A + 32KB B
#define MM_SMEM_BYTES  98304   // 2 stages

template<int MODE, int KDIM, int NDIM>
__global__ __launch_bounds__(256)
void gemm_mma(const __half* __restrict__ A, const __half* __restrict__ Wt,
              const float* __restrict__ aux, void* __restrict__ Cv) {
    int mt = blockIdx.y;
    if (MODE >= 2 && mt >= g_n_mtiles) return;
    const __half* Wb = Wt;
    const float* bias = aux;
    if (MODE >= 2) {
        int e = g_tile_expert[mt];
        Wb   = Wt + (size_t)e * KDIM * NDIM;
        bias = aux + (size_t)e * NDIM;
    }
    extern __shared__ __align__(16) char smem[];
    uint32_t sbase = smem_u32(smem);

    int tid = threadIdx.x;
    int lane = tid & 31, wid = tid >> 5;
    int bm = mt * 128, bn = blockIdx.x * 256;

    // ---- fill mapping: rg = row group (0..31), cc = 16B chunk (0..7) ----
    int rg = tid >> 3, cc = tid & 7;
    const __half* arow[4];
    #pragma unroll
    for (int i = 0; i < 4; i++) {
        int r = rg + i * 32;
        int m = (MODE == 2) ? g_tok_of_slot[bm + r] : (bm + r);
        arow[i] = A + (size_t)m * KDIM + cc * 8;
    }
    const __half* bbase = Wb + (size_t)(bn + rg) * KDIM + cc * 8;
    uint32_t sw = (uint32_t)(((cc ^ (rg & 7)) << 4) + rg * 128);

    // ---- fragment read bases, warp grid 2 (M) x 4 (N), warp tile 64x64 ----
    int wr = wid & 1, wc = wid >> 1;
    int rowa_base = wr * 64 + (lane & 7) + ((lane >> 3) & 1) * 8;
    int lhiA = lane >> 4;
    uint32_t aswz = (uint32_t)((rowa_base & 7) << 4);
    int rowb2 = wc * 64 + (lane & 7) + ((lane >> 4) & 1) * 8;
    int lbB = (lane >> 3) & 1;
    uint32_t bswz = (uint32_t)((lane & 7) << 4);

    float acc[4][8][4];
    #pragma unroll
    for (int mi = 0; mi < 4; mi++)
        #pragma unroll
        for (int ni = 0; ni < 8; ni++)
            #pragma unroll
            for (int j = 0; j < 4; j++) acc[mi][ni][j] = 0.f;

    uint4 pa[4], pb[8];

    auto load_g = [&](int s) {
        int k0 = s * 64;
        #pragma unroll
        for (int i = 0; i < 4; i++) pa[i] = *(const uint4*)(arow[i] + k0);
        #pragma unroll
        for (int i = 0; i < 8; i++)
            pb[i] = *(const uint4*)(bbase + k0 + (size_t)i * 32 * KDIM);
    };
    auto store_s = [&](int buf) {
        char* ab = smem + buf * MM_STAGE_BYTES;
        char* bb = ab + 16384;
        #pragma unroll
        for (int i = 0; i < 4; i++)
            *(uint4*)(ab + sw + i * (32 * 128)) = pa[i];
        #pragma unroll
        for (int i = 0; i < 8; i++)
            *(uint4*)(bb + sw + i * (32 * 128)) = pb[i];
    };
    auto compute = [&](int buf) {
        uint32_t abase = sbase + buf * MM_STAGE_BYTES;
        uint32_t bbs   = abase + 16384;
        #pragma unroll
        for (int ks = 0; ks < 4; ks++) {       // 4 x k16 = 64 halves
            uint32_t af[4][4];
            #pragma unroll
            for (int mi = 0; mi < 4; mi++) {
                uint32_t addr = abase + (uint32_t)((rowa_base + mi * 16) * 128)
                              + ((((uint32_t)(ks * 2 + lhiA)) << 4) ^ aswz);
                asm volatile("ldmatrix.sync.aligned.m8n8.x4.shared.b16 {%0,%1,%2,%3}, [%4];"
                    : "=r"(af[mi][0]), "=r"(af[mi][1]), "=r"(af[mi][2]), "=r"(af[mi][3])
                    : "r"(addr));
            }
            #pragma unroll
            for (int nj = 0; nj < 4; nj++) {
                uint32_t bf0, bf1, bf2, bf3;
                uint32_t addr = bbs + (uint32_t)((rowb2 + nj * 16) * 128)
                              + ((((uint32_t)(ks * 2 + lbB)) << 4) ^ bswz);
                asm volatile("ldmatrix.sync.aligned.m8n8.x4.shared.b16 {%0,%1,%2,%3}, [%4];"
                    : "=r"(bf0), "=r"(bf1), "=r"(bf2), "=r"(bf3) : "r"(addr));
                #pragma unroll
                for (int mi = 0; mi < 4; mi++) {
                    asm volatile("mma.sync.aligned.m16n8k16.row.col.f32.f16.f16.f32 "
                        "{%0,%1,%2,%3}, {%4,%5,%6,%7}, {%8,%9}, {%0,%1,%2,%3};"
                        : "+f"(acc[mi][2*nj][0]), "+f"(acc[mi][2*nj][1]),
                          "+f"(acc[mi][2*nj][2]), "+f"(acc[mi][2*nj][3])
                        : "r"(af[mi][0]), "r"(af[mi][1]), "r"(af[mi][2]), "r"(af[mi][3]),
                          "r"(bf0), "r"(bf1));
                    asm volatile("mma.sync.aligned.m16n8k16.row.col.f32.f16.f16.f32 "
                        "{%0,%1,%2,%3}, {%4,%5,%6,%7}, {%8,%9}, {%0,%1,%2,%3};"
                        : "+f"(acc[mi][2*nj+1][0]), "+f"(acc[mi][2*nj+1][1]),
                          "+f"(acc[mi][2*nj+1][2]), "+f"(acc[mi][2*nj+1][3])
                        : "r"(af[mi][0]), "r"(af[mi][1]), "r"(af[mi][2]), "r"(af[mi][3]),
                          "r"(bf2), "r"(bf3));
                }
            }
        }
    };

    const int NSTAGE = KDIM / 64;
    load_g(0);
    store_s(0);
    __syncthreads();
    for (int s = 0; s < NSTAGE; ++s) {
        int buf = s & 1;
        if (s + 1 < NSTAGE) load_g(s + 1);
        compute(buf);
        if (s + 1 < NSTAGE) store_s(buf ^ 1);
        __syncthreads();
    }

    // ---- epilogue ----
    int qr = lane >> 2, c2 = (lane & 3) * 2;
    __half* Ch = (__half*)Cv;
    float*  Cf = (float*)Cv;
    #pragma unroll
    for (int mi = 0; mi < 4; mi++) {
        int r0 = bm + wr * 64 + mi * 16 + qr;
        #pragma unroll
        for (int ni = 0; ni < 8; ni++) {
            int col = bn + wc * 64 + ni * 8 + c2;
            float v0 = acc[mi][ni][0], v1 = acc[mi][ni][1];
            float v2 = acc[mi][ni][2], v3 = acc[mi][ni][3];
            if (MODE == 1) {
                float2 ra = *(const float2*)(aux + (size_t)r0 * NDIM + col);
                float2 rb = *(const float2*)(aux + (size_t)(r0 + 8) * NDIM + col);
                v0 += ra.x; v1 += ra.y; v2 += rb.x; v3 += rb.y;
            }
            if (MODE >= 2) {
                float2 bz = *(const float2*)(bias + col);
                v0 += bz.x; v1 += bz.y; v2 += bz.x; v3 += bz.y;
                if (MODE == 2) {
                    v0 = gelu_tanh(v0); v1 = gelu_tanh(v1);
                    v2 = gelu_tanh(v2); v3 = gelu_tanh(v3);
                }
            }
            if (MODE == 0 || MODE == 2) {
                __half2 h0; h0.x = __float2half_rn(v0); h0.y = __float2half_rn(v1);
                __half2 h1; h1.x = __float2half_rn(v2); h1.y = __float2half_rn(v3);
                *(__half2*)(Ch + (size_t)r0 * NDIM + col)       = h0;
                *(__half2*)(Ch + (size_t)(r0 + 8) * NDIM + col) = h1;
            } else {
                *(float2*)(Cf + (size_t)r0 * NDIM + col)       = make_float2(v0, v1);
                *(float2*)(Cf + (size_t)(r0 + 8) * NDIM + col) = make_float2(v2, v3);
            }
        }
    }
}

// ---------------- LayerNorm ----------------
// y: fp16 (GEMM operand). If DUAL, y_raw gets the unrounded fp32 (router input).
template<bool DUAL>
__global__ __launch_bounds__(256)
void ln_kernel(const float* __restrict__ x, const float* __restrict__ g,
               const float* __restrict__ b, __half* __restrict__ y,
               float* __restrict__ y_raw) {
    int n = blockIdx.x;
    int tid = threadIdx.x;
    const float4* xr = (const float4*)(x + (size_t)n * DD);
    float4 v = xr[tid];
    float s  = v.x + v.y + v.z + v.w;
    float sq = v.x*v.x + v.y*v.y + v.z*v.z + v.w*v.w;
    __shared__ float red[2][8];
    int lane = tid & 31, wid = tid >> 5;
    #pragma unroll
    for (int o = 16; o > 0; o >>= 1) {
        s  += __shfl_down_sync(0xffffffffu, s,  o);
        sq += __shfl_down_sync(0xffffffffu, sq, o);
    }
    if (lane == 0) { red[0][wid] = s; red[1][wid] = sq; }
    __syncthreads();
    if (wid == 0) {
        float a = (lane < 8) ? red[0][lane] : 0.f;
        float c = (lane < 8) ? red[1][lane] : 0.f;
        #pragma unroll
        for (int o = 4; o > 0; o >>= 1) {
            a += __shfl_down_sync(0xffffffffu, a, o);
            c += __shfl_down_sync(0xffffffffu, c, o);
        }
        if (lane == 0) { red[0][0] = a; red[1][0] = c; }
    }
    __syncthreads();
    float mean = red[0][0] * (1.0f / DD);
    float var  = red[1][0] * (1.0f / DD) - mean * mean;
    float rstd = rsqrtf(var + 1e-5f);
    float4 gv = ((const float4*)g)[tid];
    float4 bv = ((const float4*)b)[tid];
    float4 o;
    o.x = (v.x - mean) * rstd * gv.x + bv.x;
    o.y = (v.y - mean) * rstd * gv.y + bv.y;
    o.z = (v.z - mean) * rstd * gv.z + bv.z;
    o.w = (v.w - mean) * rstd * gv.w + bv.w;
    if (DUAL)
        ((float4*)(y_raw + (size_t)n * DD))[tid] = o;
    __half2 h0; h0.x = __float2half_rn(o.x); h0.y = __float2half_rn(o.y);
    __half2 h1; h1.x = __float2half_rn(o.z); h1.y = __float2half_rn(o.w);
    __half2* yp = (__half2*)(y + (size_t)n * DD);
    yp[tid * 2]     = h0;
    yp[tid * 2 + 1] = h1;
}

// ---------------- causal flash attention (fp16 mma.sync) ----------------
// Block: (qt, h, b), 128 threads (4 warps). Tiles 64x64 fp16.
// smem: Q@0 (8K), K@8K, V^T@16K, P@24K (2K/warp). Total 32KB static.
__global__ __launch_bounds__(128)
void attn_mma_kernel(const __half* __restrict__ qkv, __half* __restrict__ o) {
    __shared__ __align__(16) char smem[32768];
    uint32_t sbase = smem_u32(smem);
    const int Qo = 0, Ko = 8192, Vo = 16384, Po = 24576;
    int qt = blockIdx.x, h = blockIdx.y, b = blockIdx.z;
    int tid = threadIdx.x, lane = tid & 31, wm = tid >> 5;

    int fr = tid >> 1;              // fill row 0..63
    int fc0 = (tid & 1) * 4;        // 16B-chunk base (4 of 8)

    // Q fill (once)
    {
        const __half* qr_ = qkv + (size_t)(b * SS + qt * 64 + fr) * (3 * DD) + h * 64;
        #pragma unroll
        for (int i = 0; i < 4; i++) {
            int cc = fc0 + i;
            uint4 v = *(const uint4*)(qr_ + cc * 8);
            *(uint4*)(smem + Qo + fr * 128 + (((cc) ^ (fr & 7)) << 4)) = v;
        }
    }

    int qr = lane >> 2, lam = lane & 3;
    int rowa = (lane & 7) + ((lane >> 3) & 1) * 8;
    int lhiA = lane >> 4;
    uint32_t aswz = (uint32_t)((rowa & 7) << 4);
    int rowb2 = (lane & 7) + ((lane >> 4) & 1) * 8;
    int lbB = (lane >> 3) & 1;
    uint32_t bswz = (uint32_t)((lane & 7) << 4);

    float acc_o[8][4];
    #pragma unroll
    for (int ni = 0; ni < 8; ni++)
        #pragma unroll
        for (int j = 0; j < 4; j++) acc_o[ni][j] = 0.f;
    float m0 = -1e30f, m1 = -1e30f, l0 = 0.f, l1 = 0.f;

    for (int kt = 0; kt <= qt; ++kt) {
        // K tile fill
        {
            const __half* kr_ = qkv + (size_t)(b * SS + kt * 64 + fr) * (3 * DD) + DD + h * 64;
            #pragma unroll
            for (int i = 0; i < 4; i++) {
                int cc = fc0 + i;
                uint4 v = *(const uint4*)(kr_ + cc * 8);
                *(uint4*)(smem + Ko + fr * 128 + (((cc) ^ (fr & 7)) << 4)) = v;
            }
        }
        // V^T fill: read V[key][d] 8 halves, scatter to [d][key]
        {
            const __half* vr_ = qkv + (size_t)(b * SS + kt * 64 + fr) * (3 * DD) + 2 * DD + h * 64;
            #pragma unroll
            for (int i = 0; i < 4; i++) {
                int d0 = (tid & 1) * 32 + i * 8;
                uint4 v = *(const uint4*)(vr_ + d0);
                const __half* hp = (const __half*)&v;
                #pragma unroll
                for (int j = 0; j < 8; j++) {
                    int dd = d0 + j;
                    *(__half*)(smem + Vo + dd * 128
                               + ((((fr >> 3) ^ (dd & 7))) << 4) + (fr & 7) * 2) = hp[j];
                }
            }
        }
        __syncthreads();

        // ---- S = Q * K^T ----
        float accs[8][4];
        #pragma unroll
        for (int ni = 0; ni < 8; ni++)
            #pragma unroll
            for (int j = 0; j < 4; j++) accs[ni][j] = 0.f;
        #pragma unroll
        for (int ks = 0; ks < 4; ks++) {
            uint32_t a0, a1, a2, a3;
            uint32_t aad = sbase + Qo + (wm * 16 + rowa) * 128
                         + ((((uint32_t)(ks * 2 + lhiA)) << 4) ^ aswz);
            asm volatile("ldmatrix.sync.aligned.m8n8.x4.shared.b16 {%0,%1,%2,%3}, [%4];"
                : "=r"(a0), "=r"(a1), "=r"(a2), "=r"(a3) : "r"(aad));
            #pragma unroll
            for (int nj = 0; nj < 4; nj++) {
                uint32_t bf0, bf1, bf2, bf3;
                uint32_t bad = sbase + Ko + (rowb2 + nj * 16) * 128
                             + ((((uint32_t)(ks * 2 + lbB)) << 4) ^ bswz);
                asm volatile("ldmatrix.sync.aligned.m8n8.x4.shared.b16 {%0,%1,%2,%3}, [%4];"
                    : "=r"(bf0), "=r"(bf1), "=r"(bf2), "=r"(bf3) : "r"(bad));
                asm volatile("mma.sync.aligned.m16n8k16.row.col.f32.f16.f16.f32 "
                    "{%0,%1,%2,%3}, {%4,%5,%6,%7}, {%8,%9}, {%0,%1,%2,%3};"
                    : "+f"(accs[2*nj][0]), "+f"(accs[2*nj][1]),
                      "+f"(accs[2*nj][2]), "+f"(accs[2*nj][3])
                    : "r"(a0), "r"(a1), "r"(a2), "r"(a3), "r"(bf0), "r"(bf1));
                asm volatile("mma.sync.aligned.m16n8k16.row.col.f32.f16.f16.f32 "
                    "{%0,%1,%2,%3}, {%4,%5,%6,%7}, {%8,%9}, {%0,%1,%2,%3};"
                    : "+f"(accs[2*nj+1][0]), "+f"(accs[2*nj+1][1]),
                      "+f"(accs[2*nj+1][2]), "+f"(accs[2*nj+1][3])
                    : "r"(a0), "r"(a1), "r"(a2), "r"(a3), "r"(bf2), "r"(bf3));
            }
        }

        // ---- scale + causal mask + online softmax ----
        float tm0 = -1e30f, tm1 = -1e30f;
        #pragma unroll
        for (int ni = 0; ni < 8; ni++) {
            #pragma unroll
            for (int j = 0; j < 4; j++) {
                float s = accs[ni][j] * 0.125f;
                int col = ni * 8 + 2 * lam + (j & 1);
                int rl  = wm * 16 + qr + (j >> 1) * 8;
                if (kt == qt && col > rl) s = -1e30f;
                accs[ni][j] = s;
                if ((j >> 1) == 0) tm0 = fmaxf(tm0, s);
                else               tm1 = fmaxf(tm1, s);
            }
        }
        tm0 = fmaxf(tm0, __shfl_xor_sync(0xffffffffu, tm0, 1));
        tm0 = fmaxf(tm0, __shfl_xor_sync(0xffffffffu, tm0, 2));
        tm1 = fmaxf(tm1, __shfl_xor_sync(0xffffffffu, tm1, 1));
        tm1 = fmaxf(tm1, __shfl_xor_sync(0xffffffffu, tm1, 2));
        float mn0 = fmaxf(m0, tm0), mn1 = fmaxf(m1, tm1);
        float c0 = __expf(m0 - mn0), c1 = __expf(m1 - mn1);
        m0 = mn0; m1 = mn1;

        char* pw = smem + Po + wm * 2048;
        float ls0 = 0.f, ls1 = 0.f;
        #pragma unroll
        for (int ni = 0; ni < 8; ni++) {
            #pragma unroll
            for (int j = 0; j < 4; j++) {
                float mrow = (j >> 1) ? m1 : m0;
                __half ph = __float2half_rn(__expf(accs[ni][j] - mrow));
                float pr = __half2float(ph);
                if (j >> 1) ls1 += pr; else ls0 += pr;
                int col = ni * 8 + 2 * lam + (j & 1);
                int r   = qr + (j >> 1) * 8;
                *(__half*)(pw + r * 128 + ((((col >> 3) ^ (r & 7))) << 4) + (col & 7) * 2) = ph;
            }
        }
        ls0 += __shfl_xor_sync(0xffffffffu, ls0, 1);
        ls0 += __shfl_xor_sync(0xffffffffu, ls0, 2);
        ls1 += __shfl_xor_sync(0xffffffffu, ls1, 1);
        ls1 += __shfl_xor_sync(0xffffffffu, ls1, 2);
        l0 = l0 * c0 + ls0;
        l1 = l1 * c1 + ls1;
        #pragma unroll
        for (int ni = 0; ni < 8; ni++) {
            acc_o[ni][0] *= c0; acc_o[ni][1] *= c0;
            acc_o[ni][2] *= c1; acc_o[ni][3] *= c1;
        }
        __syncwarp();

        // ---- O += P * V ----
        uint32_t pwb = sbase + Po + wm * 2048;
        #pragma unroll
        for (int ks = 0; ks < 4; ks++) {
            uint32_t a0, a1, a2, a3;
            uint32_t aad = pwb + rowa * 128
                         + ((((uint32_t)(ks * 2 + lhiA)) << 4) ^ aswz);
            asm volatile("ldmatrix.sync.aligned.m8n8.x4.shared.b16 {%0,%1,%2,%3}, [%4];"
                : "=r"(a0), "=r"(a1), "=r"(a2), "=r"(a3) : "r"(aad));
            #pragma unroll
            for (int nj = 0; nj < 4; nj++) {
                uint32_t bf0, bf1, bf2, bf3;
                uint32_t bad = sbase + Vo + (rowb2 + nj * 16) * 128
                             + ((((uint32_t)(ks * 2 + lbB)) << 4) ^ bswz);
                asm volatile("ldmatrix.sync.aligned.m8n8.x4.shared.b16 {%0,%1,%2,%3}, [%4];"
                    : "=r"(bf0), "=r"(bf1), "=r"(bf2), "=r"(bf3) : "r"(bad));
                asm volatile("mma.sync.aligned.m16n8k16.row.col.f32.f16.f16.f32 "
                    "{%0,%1,%2,%3}, {%4,%5,%6,%7}, {%8,%9}, {%0,%1,%2,%3};"
                    : "+f"(acc_o[2*nj][0]), "+f"(acc_o[2*nj][1]),
                      "+f"(acc_o[2*nj][2]), "+f"(acc_o[2*nj][3])
                    : "r"(a0), "r"(a1), "r"(a2), "r"(a3), "r"(bf0), "r"(bf1));
                asm volatile("mma.sync.aligned.m16n8k16.row.col.f32.f16.f16.f32 "
                    "{%0,%1,%2,%3}, {%4,%5,%6,%7}, {%8,%9}, {%0,%1,%2,%3};"
                    : "+f"(acc_o[2*nj+1][0]), "+f"(acc_o[2*nj+1][1]),
                      "+f"(acc_o[2*nj+1][2]), "+f"(acc_o[2*nj+1][3])
                    : "r"(a0), "r"(a1), "r"(a2), "r"(a3), "r"(bf2), "r"(bf3));
            }
        }
        __syncthreads();
    }

    // ---- epilogue: O /= l, write fp16 ----
    float i0 = 1.f / l0, i1 = 1.f / l1;
    int r0 = b * SS + qt * 64 + wm * 16 + qr;
    #pragma unroll
    for (int ni = 0; ni < 8; ni++) {
        int col = h * 64 + ni * 8 + 2 * lam;
        __half2 w0; w0.x = __float2half_rn(acc_o[ni][0] * i0); w0.y = __float2half_rn(acc_o[ni][1] * i0);
        __half2 w1; w1.x = __float2half_rn(acc_o[ni][2] * i1); w1.y = __float2half_rn(acc_o[ni][3] * i1);
        *(__half2*)(o + (size_t)r0 * DD + col)       = w0;
        *(__half2*)(o + (size_t)(r0 + 8) * DD + col) = w1;
    }
}

// ---------------- gate: logits + top-2 (uses UNROUNDED moe input) ----------------
__global__ __launch_bounds__(128)
void gate_kernel(const float* __restrict__ moe_raw, const float* __restrict__ w_gate) {
    int lane = threadIdx.x & 31, wid = threadIdx.x >> 5;
    int n = blockIdx.x * 4 + wid;
    float acc[EE];
    #pragma unroll
    for (int e = 0; e < EE; e++) acc[e] = 0.f;
    const float* xr = moe_raw + (size_t)n * DD;
    for (int d = lane; d < DD; d += 32) {
        float xv = xr[d];
        const float* wg = w_gate + (size_t)d * EE;
        #pragma unroll
        for (int e = 0; e < EE; e++) acc[e] += xv * wg[e];
    }
    #pragma unroll
    for (int e = 0; e < EE; e++) {
        #pragma unroll
        for (int o = 16; o > 0; o >>= 1)
            acc[e] += __shfl_down_sync(0xffffffffu, acc[e], o);
    }
    if (lane == 0) {
        int i0 = 0;
        #pragma unroll
        for (int e = 1; e < EE; e++) if (acc[e] > acc[i0]) i0 = e;
        int i1 = (i0 == 0) ? 1 : 0;
        #pragma unroll
        for (int e = 0; e < EE; e++)
            if (e != i0 && acc[e] > acc[i1]) i1 = e;
        float w0 = 1.f / (1.f + __expf(acc[i1] - acc[i0]));
        g_top_e[2*n]   = i0;  g_top_e[2*n+1]   = i1;
        g_top_w[2*n]   = w0;  g_top_w[2*n+1]   = 1.f - w0;
    }
}

// ---------------- routing ----------------
__global__ void counts_kernel() {
    __shared__ int cnt;
    if (threadIdx.x == 0) cnt = 0;
    __syncthreads();
    int e = blockIdx.x;
    int local = 0;
    for (int n = threadIdx.x; n < NTOK; n += 256)
        if (g_top_e[2*n] == e || g_top_e[2*n+1] == e) local++;
    atomicAdd(&cnt, local);
    __syncthreads();
    if (threadIdx.x == 0) g_counts[e] = cnt;
}

__global__ void offsets_kernel() {
    int off = 0;
    for (int e = 0; e < EE; ++e) {
        g_pad_off[e] = off;
        int seg = ((g_counts[e] + 127) >> 7) << 7;
        int t0 = off >> 7, t1 = (off + seg) >> 7;
        for (int t = t0; t < t1; ++t) g_tile_expert[t] = e;
        off += seg;
    }
    g_pad_off[EE] = off;
    g_n_mtiles = off >> 7;
}

__global__ __launch_bounds__(128)
void compact_kernel() {
    int e = blockIdx.x;
    int tid = threadIdx.x;
    int lane = tid & 31, wid = tid >> 5;
    __shared__ int warp_cnt[4];
    __shared__ int running;
    if (tid == 0) running = 0;
    __syncthreads();
    int base = g_pad_off[e];
    for (int c = 0; c < NTOK / 128; ++c) {
        int n = c * 128 + tid;
        int k = -1;
        if (g_top_e[2*n] == e) k = 0;
        else if (g_top_e[2*n+1] == e) k = 1;
        unsigned msk = __ballot_sync(0xffffffffu, k >= 0);
        int rank = __popc(msk & ((1u << lane) - 1));
        if (lane == 0) warp_cnt[wid] = __popc(msk);
        __syncthreads();
        int wbase = 0;
        #pragma unroll
        for (int w = 0; w < 4; ++w) if (w < wid) wbase += warp_cnt[w];
        int cur = running;
        if (k >= 0) {
            int slot = base + cur + wbase + rank;
            g_tok_of_slot[slot] = n;
            g_slot_of[2*n + k]  = slot;
        }
        __syncthreads();
        if (tid == 0)
            running = cur + warp_cnt[0] + warp_cnt[1] + warp_cnt[2] + warp_cnt[3];
        __syncthreads();
    }
    int cnt = running;
    int end = g_pad_off[e + 1];
    for (int s = base + cnt + tid; s < end; s += 128) g_tok_of_slot[s] = 0;
}

// ---------------- combine ----------------
__global__ __launch_bounds__(256)
void combine_kernel(const float* __restrict__ xres, const float* __restrict__ y,
                    float* __restrict__ out) {
    int n = blockIdx.x;
    int s0 = g_slot_of[2*n], s1 = g_slot_of[2*n+1];
    float wa = g_top_w[2*n], wb = g_top_w[2*n+1];
    int tid = threadIdx.x;
    float4 a  = ((const float4*)(xres + (size_t)n  * DD))[tid];
    float4 y0 = ((const float4*)(y + (size_t)s0 * DD))[tid];
    float4 y1 = ((const float4*)(y + (size_t)s1 * DD))[tid];
    float4 r;
    r.x = a.x + wa * y0.x + wb * y1.x;
    r.y = a.y + wa * y0.y + wb * y1.y;
    r.z = a.z + wa * y0.z + wb * y1.z;
    r.w = a.w + wa * y0.w + wb * y1.w;
    ((float4*)(out + (size_t)n * DD))[tid] = r;
}

// ---------------- launch ----------------
extern "C" void kernel_launch(void* const* d_in, const int* in_sizes, int n_in,
                              void* d_out, int out_size) {
    const float* x      = (const float*)d_in[0];
    const float* ln1_g  = (const float*)d_in[1];
    const float* ln1_b  = (const float*)d_in[2];
    const float* ln2_g  = (const float*)d_in[3];
    const float* ln2_b  = (const float*)d_in[4];
    const float* w_qkv  = (const float*)d_in[5];
    const float* w_o    = (const float*)d_in[6];
    const float* w_gate = (const float*)d_in[7];
    const float* w1     = (const float*)d_in[8];
    const float* b1     = (const float*)d_in[9];
    const float* w2     = (const float*)d_in[10];
    const float* b2     = (const float*)d_in[11];
    float* out = (float*)d_out;

    __half* p_hln;  cudaGetSymbolAddress((void**)&p_hln,  g_hln);
    __half* p_qkv;  cudaGetSymbolAddress((void**)&p_qkv,  g_qkv);
    __half* p_attn; cudaGetSymbolAddress((void**)&p_attn, g_attn);
    float*  p_xres; cudaGetSymbolAddress((void**)&p_xres, g_xres);
    __half* p_moein;cudaGetSymbolAddress((void**)&p_moein,g_moein);
    float*  p_moeraw;cudaGetSymbolAddress((void**)&p_moeraw,g_moeraw);
    __half* p_h1;   cudaGetSymbolAddress((void**)&p_h1,   g_h1);
    float*  p_y;    cudaGetSymbolAddress((void**)&p_y,    g_y);
    __half* p_wqkv; cudaGetSymbolAddress((void**)&p_wqkv, g_wt_qkv);
    __half* p_wo;   cudaGetSymbolAddress((void**)&p_wo,   g_wt_o);
    __half* p_w1;   cudaGetSymbolAddress((void**)&p_w1,   g_wt1);
    __half* p_w2;   cudaGetSymbolAddress((void**)&p_w2,   g_wt2);

    cudaFuncSetAttribute(gemm_mma<0, DD, 3*DD>, cudaFuncAttributeMaxDynamicSharedMemorySize, MM_SMEM_BYTES);
    cudaFuncSetAttribute(gemm_mma<1, DD, DD>,   cudaFuncAttributeMaxDynamicSharedMemorySize, MM_SMEM_BYTES);
    cudaFuncSetAttribute(gemm_mma<2, DD, FF>,   cudaFuncAttributeMaxDynamicSharedMemorySize, MM_SMEM_BYTES);
    cudaFuncSetAttribute(gemm_mma<3, FF, DD>,   cudaFuncAttributeMaxDynamicSharedMemorySize, MM_SMEM_BYTES);

    dim3 tb(32, 8);
    // 0. weight transpose + fp16 convert
    transpose_round<<<dim3(3*DD/32, DD/32, 1),  tb>>>(w_qkv, p_wqkv, DD, 3*DD);
    transpose_round<<<dim3(DD/32,   DD/32, 1),  tb>>>(w_o,   p_wo,   DD, DD);
    transpose_round<<<dim3(FF/32,   DD/32, EE), tb>>>(w1,    p_w1,   DD, FF);
    transpose_round<<<dim3(DD/32,   FF/32, EE), tb>>>(w2,    p_w2,   FF, DD);
    // 1. LN1
    ln_kernel<false><<<NTOK, 256>>>(x, ln1_g, ln1_b, p_hln, nullptr);
    // 2. QKV GEMM (fp16 out)
    gemm_mma<0, DD, 3*DD><<<dim3(3*DD/256, NTOK/128), 256, MM_SMEM_BYTES>>>(p_hln, p_wqkv, nullptr, p_qkv);
    // 3. causal attention (fp16 tensor cores)
    attn_mma_kernel<<<dim3(SS/64, HH, BB), 128>>>(p_qkv, p_attn);
    // 4. O-proj + residual (fp32 out)
    gemm_mma<1, DD, DD><<<dim3(DD/256, NTOK/128), 256, MM_SMEM_BYTES>>>(p_attn, p_wo, x, p_xres);
    // 5. LN2 (dual: fp16 for GEMM, raw fp32 for router)
    ln_kernel<true><<<NTOK, 256>>>(p_xres, ln2_g, ln2_b, p_moein, p_moeraw);
    // 6. gate + top-2 on RAW activations
    gate_kernel<<<NTOK/4, 128>>>(p_moeraw, w_gate);
    // 7-9. routing
    counts_kernel<<<EE, 256>>>();
    offsets_kernel<<<1, 1>>>();
    compact_kernel<<<EE, 128>>>();
    // 10. MoE up: gelu(x @ w1[e] + b1[e]) (fp16 out)
    gemm_mma<2, DD, FF><<<dim3(FF/256, MAXMT), 256, MM_SMEM_BYTES>>>(p_moein, p_w1, b1, p_h1);
    // 11. MoE down: h1 @ w2[e] + b2[e] (fp32 out)
    gemm_mma<3, FF, DD><<<dim3(DD/256, MAXMT), 256, MM_SMEM_BYTES>>>(p_h1, p_w2, b2, p_y);
    // 12. combine + residual
    combine_kernel<<<NTOK, 256>>>(p_xres, p_y, out);
}